// round 11
// baseline (speedup 1.0000x reference)
#include <cuda_runtime.h>
#include <cuda_bf16.h>
#include <stdint.h>

// Problem constants
#define VALUE_VOCAB 100000
#define NCTX      200
#define D         128
#define F         384
#define OUTD      128
#define THREADS   512
#define TILE_N    64
#define NTILES    4            // 4 x 64 = 256 rows (padded; invalid rows esc=0)

#define CTX_BSTRIDE  400       // bytes per ctx/W row (384 fp8 + 16 pad)

// ---- smem layout (bytes) ----
#define OFF_W      0
#define SZ_W       (D * CTX_BSTRIDE)              // 51200
#define OFF_CTX0   (OFF_W + SZ_W)                 // 51200
#define SZ_CTX     (TILE_N * CTX_BSTRIDE)         // 25600
#define OFF_CTX1   (OFF_CTX0 + SZ_CTX)            // 76800
#define OFF_OFS    (OFF_CTX1 + SZ_CTX)            // 102400 : 3*256*4 = 3072
#define OFF_AV     (OFF_OFS + 3072)               // 512
#define OFF_SP     (OFF_AV + 512)                 // 2048
#define OFF_ESC    (OFF_SP + 2048)                // 256
#define OFF_CODEP  (OFF_ESC + 256)                // 1024
#define OFF_CODES  (OFF_CODEP + 1024)             // 512
#define OFF_ZS     (OFF_CODES + 512)              // 1536
#define OFF_EP     (OFF_ZS + 1536)                // 64
#define SMEM_BYTES (OFF_EP + 64)                  // 111424 (2 CTAs/SM)

// W pre-converted to e4m3, row stride 400 B
__device__ __align__(16) unsigned char g_Wf8[SZ_W];
// value_vocab pre-converted to e4m3, rows of 128 B
__device__ __align__(16) unsigned char g_valf8[(size_t)VALUE_VOCAB * 128];

__device__ __forceinline__ uint32_t pack4_e4m3(float4 v) {
    uint16_t lo, hi;
    asm("cvt.rn.satfinite.e4m3x2.f32 %0, %1, %2;" : "=h"(lo) : "f"(v.y), "f"(v.x));
    asm("cvt.rn.satfinite.e4m3x2.f32 %0, %1, %2;" : "=h"(hi) : "f"(v.w), "f"(v.z));
    return (uint32_t)lo | ((uint32_t)hi << 16);
}

// merged prep: blocks 0-47 convert W, blocks 48+ convert value_vocab
__global__ void prep_kernel(const float* __restrict__ W,
                            const float* __restrict__ vv) {
    if (blockIdx.x < 48) {
        int i = blockIdx.x * 256 + threadIdx.x;      // 0..12287 (128 rows x 96 quads)
        int d = i / 96, j = i % 96;
        float4 v = ((const float4*)W)[i];
        *(uint32_t*)(g_Wf8 + d * CTX_BSTRIDE + j * 4) = pack4_e4m3(v);
    } else {
        size_t q0 = ((size_t)(blockIdx.x - 48) * 256 + threadIdx.x) * 4;
        uint32_t o[4];
#pragma unroll
        for (int u = 0; u < 4; u++)
            o[u] = pack4_e4m3(((const float4*)vv)[q0 + u]);
        *(uint4*)(g_valf8 + q0 * 4) = make_uint4(o[0], o[1], o[2], o[3]);
    }
}

__device__ __forceinline__ float fast_tanhf(float x) {
    float y; asm("tanh.approx.f32 %0, %1;" : "=f"(y) : "f"(x)); return y;
}
__device__ __forceinline__ void mma_f8(float* acc, uint32_t a0, uint32_t a1,
                                       uint32_t a2, uint32_t a3,
                                       uint32_t b0, uint32_t b1) {
    asm volatile(
        "mma.sync.aligned.m16n8k32.row.col.f32.e4m3.e4m3.f32 "
        "{%0,%1,%2,%3},{%4,%5,%6,%7},{%8,%9},{%0,%1,%2,%3};"
        : "+f"(acc[0]), "+f"(acc[1]), "+f"(acc[2]), "+f"(acc[3])
        : "r"(a0), "r"(a1), "r"(a2), "r"(a3), "r"(b0), "r"(b1));
}
__device__ __forceinline__ void ldsm_x4(uint32_t& r0, uint32_t& r1,
                                        uint32_t& r2, uint32_t& r3, uint32_t saddr) {
    asm volatile("ldmatrix.sync.aligned.m8n8.x4.shared.b16 {%0,%1,%2,%3}, [%4];"
                 : "=r"(r0), "=r"(r1), "=r"(r2), "=r"(r3) : "r"(saddr));
}
__device__ __forceinline__ float4 ldg_nc_v4(const float* p) {
    float4 r;
    asm volatile("ld.global.nc.v4.f32 {%0,%1,%2,%3}, [%4];"
                 : "=f"(r.x), "=f"(r.y), "=f"(r.z), "=f"(r.w) : "l"(p));
    return r;
}
__device__ __forceinline__ void cp16(uint32_t sdst, const void* gsrc) {
    asm volatile("cp.async.cg.shared.global [%0], [%1], 16;"
                 :: "r"(sdst), "l"(gsrc));
}

__global__ void __launch_bounds__(THREADS, 2)
acv_fused_kernel(const int* __restrict__ xs_xt,
                 const int* __restrict__ path_idx,
                 const float* __restrict__ path_vocab,
                 const float* __restrict__ att_vec,
                 const float* __restrict__ dense_w,
                 const float* __restrict__ dense_b,
                 float* __restrict__ out)
{
    extern __shared__ unsigned char smem[];
    uint32_t* vso = (uint32_t*)(smem + OFF_OFS);         // xs value-row byte offsets
    uint32_t* vpo = vso + 256;                           // path row byte offsets
    uint32_t* vto = vpo + 256;                           // xt value-row byte offsets
    float* avs   = (float*)(smem + OFF_AV);
    float* sp    = (float*)(smem + OFF_SP);
    float* esc   = (float*)(smem + OFF_ESC);
    float* codep = (float*)(smem + OFF_CODEP);
    float* codes = (float*)(smem + OFF_CODES);
    float* zs    = (float*)(smem + OFF_ZS);
    float* ep    = (float*)(smem + OFF_EP);

    const int tid  = threadIdx.x;
    const int b    = blockIdx.x;
    const int lane = tid & 31;
    const int warp = tid >> 5;

    // ---- cp.async W (pre-converted fp8) into smem ----
    {
        uint32_t ws = (uint32_t)__cvta_generic_to_shared(smem + OFF_W);
        const char* wg = (const char*)g_Wf8;
        for (int i = tid; i < SZ_W / 16; i += THREADS)
            cp16(ws + i * 16, wg + i * 16);
        asm volatile("cp.async.commit_group;");
    }

    // ---- stage row byte-offsets (padded to 256 rows; pads -> row 0) ----
    for (int i = tid; i < 2 * NCTX; i += THREADS) {
        uint32_t o = (uint32_t)xs_xt[b * 2 * NCTX + i] * 128u;
        if (i & 1) vto[i >> 1] = o; else vso[i >> 1] = o;
    }
    if (tid < NCTX) vpo[tid] = (uint32_t)path_idx[b * NCTX + tid] * 512u;
    if (tid < 56) { vso[NCTX + tid] = 0; vpo[NCTX + tid] = 0; vto[NCTX + tid] = 0; }
    if (tid < D) avs[tid] = att_vec[tid];
    __syncthreads();

    const uint32_t ctx_s = (uint32_t)__cvta_generic_to_shared(smem + OFF_CTX0);
    const uint32_t w_s   = (uint32_t)__cvta_generic_to_shared(smem + OFF_W);
    const char* valb  = (const char*)g_valf8;
    const char* pathb = (const char*)path_vocab;

    // gather role: 8 threads per row
    const int grow = tid >> 3;
    const int gsub = tid & 7;
    const uint32_t crow_base = ctx_s + grow * CTX_BSTRIDE;

    // ---- prologue: xs/xt of tile 0 via cp.async into buf0 ----
    {
        uint32_t so = vso[grow], to = vto[grow];
        cp16(crow_base + gsub * 16,       valb + so + gsub * 16);
        cp16(crow_base + 256 + gsub * 16, valb + to + gsub * 16);
        asm volatile("cp.async.commit_group;");
    }

    // ---- warp tiling: 2 m-warps (32 rows) x 8 n-warps (16 cols) ----
    const int mwarp = warp & 1;
    const int nwarp = warp >> 1;
    const int g  = lane >> 2;
    const int tg = lane & 3;

    const uint32_t a_off0 = (uint32_t)((mwarp * 32 + (lane & 15)) * CTX_BSTRIDE + (lane >> 4) * 16);
    const uint32_t a_off1 = a_off0 + 16 * CTX_BSTRIDE;
    const int bc = ((lane >> 4) << 3) + (lane & 7);
    const uint32_t b_off = (uint32_t)((nwarp * 16 + bc) * CTX_BSTRIDE + ((lane >> 3) & 1) * 16);

    float av4[4];
#pragma unroll
    for (int jj = 0; jj < 2; jj++) {
        int col = nwarp * 16 + jj * 8 + tg * 2;
        av4[jj * 2]     = avs[col];
        av4[jj * 2 + 1] = avs[col + 1];
    }

    float cpart[4] = {0.f, 0.f, 0.f, 0.f};
    float resum = 0.f;

    for (int t = 0; t < NTILES; t++) {
        const int n0 = t * TILE_N;
        const bool hn = (t + 1 < NTILES);
        const uint32_t cbuf = (t & 1) * SZ_CTX;
        const uint32_t nbuf = ((t + 1) & 1) * SZ_CTX;

        // ---- prefetch xs/xt of tile t+1 (zero registers; lands during GEMM) ----
        if (hn) {
            int nr = n0 + TILE_N + grow;
            uint32_t so = vso[nr], to = vto[nr];
            cp16(crow_base + nbuf + gsub * 16,       valb + so + gsub * 16);
            cp16(crow_base + nbuf + 256 + gsub * 16, valb + to + gsub * 16);
            asm volatile("cp.async.commit_group;");
        }

        // ---- in-phase path gather for tile t (regs die before GEMM) ----
        {
            const float* pr = (const float*)(pathb + vpo[n0 + grow]);
            float4 f0 = ldg_nc_v4(pr + gsub * 4);
            float4 f1 = ldg_nc_v4(pr + (gsub + 8) * 4);
            float4 f2 = ldg_nc_v4(pr + (gsub + 16) * 4);
            float4 f3 = ldg_nc_v4(pr + (gsub + 24) * 4);
            unsigned char* crow = smem + OFF_CTX0 + cbuf + grow * CTX_BSTRIDE + 128;
            *(uint32_t*)(crow + gsub * 4)        = pack4_e4m3(f0);
            *(uint32_t*)(crow + (gsub + 8) * 4)  = pack4_e4m3(f1);
            *(uint32_t*)(crow + (gsub + 16) * 4) = pack4_e4m3(f2);
            *(uint32_t*)(crow + (gsub + 24) * 4) = pack4_e4m3(f3);
        }
        // xs/xt for tile t were committed last iteration (or prologue):
        // pending groups now: [tile t+1 (just committed)], [tile t] already ...
        // wait until only the newest (t+1) group may remain.
        if (hn) asm volatile("cp.async.wait_group 1;");
        else    asm volatile("cp.async.wait_group 0;");
        __syncthreads();

        // ---- GEMM: acc[m][jj][c], 12 k32-steps ----
        float acc[2][2][4];
#pragma unroll
        for (int m = 0; m < 2; m++)
#pragma unroll
            for (int jj = 0; jj < 2; jj++)
#pragma unroll
                for (int c = 0; c < 4; c++) acc[m][jj][c] = 0.f;

#pragma unroll
        for (int kk = 0; kk < 12; kk++) {
            uint32_t a[2][4], bq[4];
            ldsm_x4(a[0][0], a[0][1], a[0][2], a[0][3], ctx_s + cbuf + a_off0 + kk * 32);
            ldsm_x4(a[1][0], a[1][1], a[1][2], a[1][3], ctx_s + cbuf + a_off1 + kk * 32);
            ldsm_x4(bq[0], bq[1], bq[2], bq[3], w_s + b_off + kk * 32);
#pragma unroll
            for (int m = 0; m < 2; m++) {
                mma_f8(acc[m][0], a[m][0], a[m][1], a[m][2], a[m][3], bq[0], bq[1]);
                mma_f8(acc[m][1], a[m][0], a[m][1], a[m][2], a[m][3], bq[2], bq[3]);
            }
        }

        // ---- tanh in place + score partials ----
#pragma unroll
        for (int m = 0; m < 2; m++)
#pragma unroll
            for (int jj = 0; jj < 2; jj++)
#pragma unroll
                for (int c = 0; c < 4; c++)
                    acc[m][jj][c] = fast_tanhf(acc[m][jj][c]);

#pragma unroll
        for (int m = 0; m < 2; m++) {
#pragma unroll
            for (int h = 0; h < 2; h++) {
                float p = 0.f;
#pragma unroll
                for (int jj = 0; jj < 2; jj++) {
                    p += av4[jj * 2]     * acc[m][jj][h * 2];
                    p += av4[jj * 2 + 1] * acc[m][jj][h * 2 + 1];
                }
                p += __shfl_xor_sync(0xFFFFFFFFu, p, 1);
                p += __shfl_xor_sync(0xFFFFFFFFu, p, 2);
                if (tg == 0) {
                    int row = mwarp * 32 + m * 16 + h * 8 + g;
                    sp[row * 8 + nwarp] = p;
                }
            }
        }
        __syncthreads();

        if (tid < TILE_N) {
            float s = 0.f;
#pragma unroll
            for (int w8 = 0; w8 < 8; w8++) s += sp[tid * 8 + w8];
            float e = (n0 + tid < NCTX) ? __expf(s) : 0.f;
            esc[tid] = e;
            resum += e;
        }
        __syncthreads();

        // ---- weighted accumulation from registers ----
#pragma unroll
        for (int m = 0; m < 2; m++) {
#pragma unroll
            for (int h = 0; h < 2; h++) {
                float e = esc[mwarp * 32 + m * 16 + h * 8 + g];
#pragma unroll
                for (int jj = 0; jj < 2; jj++) {
                    cpart[jj * 2]     += e * acc[m][jj][h * 2];
                    cpart[jj * 2 + 1] += e * acc[m][jj][h * 2 + 1];
                }
            }
        }
        // tile t+1's xs/xt cp.asyncs still in flight; waited at next iter top.
    }

    // ---- reduce cpart across g, write per-mwarp col partials ----
#pragma unroll
    for (int off = 4; off < 32; off <<= 1)
#pragma unroll
        for (int i = 0; i < 4; i++)
            cpart[i] += __shfl_xor_sync(0xFFFFFFFFu, cpart[i], off);
    if (g == 0) {
#pragma unroll
        for (int jj = 0; jj < 2; jj++) {
            int col = nwarp * 16 + jj * 8 + tg * 2;
            codep[col * 2 + mwarp]       = cpart[jj * 2];
            codep[(col + 1) * 2 + mwarp] = cpart[jj * 2 + 1];
        }
    }
    if (tid < TILE_N) {
        float s = resum;
#pragma unroll
        for (int off = 16; off > 0; off >>= 1)
            s += __shfl_xor_sync(0xFFFFFFFFu, s, off);
        if (lane == 0) ep[warp] = s;
    }
    __syncthreads();

    float esum = ep[0] + ep[1];
    if (tid < D) {
        float c = codep[tid * 2] + codep[tid * 2 + 1];
        codes[tid] = c / esum;
    }
    __syncthreads();

    // ---- dense + sigmoid ----
    {
        const int grp = tid >> 7, dcol = tid & 127;
        float z = 0.f;
#pragma unroll 8
        for (int d2 = 0; d2 < 32; d2++) {
            int d = grp * 32 + d2;
            z += codes[d] * dense_w[d * OUTD + dcol];
        }
        if (grp != 0) zs[(grp - 1) * 128 + dcol] = z;
        __syncthreads();
        if (grp == 0) {
            float zz = z + zs[dcol] + zs[128 + dcol] + zs[256 + dcol] + dense_b[dcol];
            out[b * OUTD + dcol] = 1.f / (1.f + __expf(-zz));
        }
    }
}

extern "C" void kernel_launch(void* const* d_in, const int* in_sizes, int n_in,
                              void* d_out, int out_size)
{
    const int*   xs_xt       = (const int*)d_in[0];
    const int*   path_idx    = (const int*)d_in[1];
    const float* value_vocab = (const float*)d_in[2];
    const float* path_vocab  = (const float*)d_in[3];
    const float* W           = (const float*)d_in[4];
    const float* att_vec     = (const float*)d_in[5];
    const float* dense_w     = (const float*)d_in[6];
    const float* dense_b     = (const float*)d_in[7];
    float*       out         = (float*)d_out;

    prep_kernel<<<48 + 3125, 256>>>(W, value_vocab);

    cudaFuncSetAttribute(acv_fused_kernel,
                         cudaFuncAttributeMaxDynamicSharedMemorySize, SMEM_BYTES);
    acv_fused_kernel<<<1024, THREADS, SMEM_BYTES>>>(
        xs_xt, path_idx, path_vocab, att_vec,
        dense_w, dense_b, out);
}

// round 12
// speedup vs baseline: 1.3357x; 1.3357x over previous
#include <cuda_runtime.h>
#include <cuda_bf16.h>
#include <stdint.h>

// Problem constants
#define VALUE_VOCAB 100000
#define NCTX      200
#define D         128
#define F         384
#define OUTD      128
#define THREADS   512
#define TILE_N    64
#define NTILES    4            // 4 x 64 = 256 rows (padded; invalid rows esc=0)

#define CTX_BSTRIDE  400       // bytes per ctx/W row (384 fp8 + 16 pad)

// ---- smem layout (bytes) ----
#define OFF_W      0
#define SZ_W       (D * CTX_BSTRIDE)              // 51200
#define OFF_CTX    (OFF_W + SZ_W)                 // 51200
#define SZ_CTX     (TILE_N * CTX_BSTRIDE)         // 25600
#define OFF_PTR    (OFF_CTX + SZ_CTX)             // 76800 : 3*256*8 = 6144
#define OFF_AV     (OFF_PTR + 6144)               // 512
#define OFF_SP     (OFF_AV + 512)                 // 2048
#define OFF_ESC    (OFF_SP + 2048)                // 256
#define OFF_CODEP  (OFF_ESC + 256)                // 1024
#define OFF_CODES  (OFF_CODEP + 1024)             // 512
#define OFF_ZS     (OFF_CODES + 512)              // 1536
#define OFF_EP     (OFF_ZS + 1536)                // 64
#define SMEM_BYTES (OFF_EP + 64)                  // ~88.6 KB (2 CTAs/SM)

// W pre-converted to e4m3, row stride 400 B
__device__ __align__(16) unsigned char g_Wf8[SZ_W];
// value_vocab pre-converted to e4m3, rows of 128 B
__device__ __align__(16) unsigned char g_valf8[(size_t)VALUE_VOCAB * 128];

__device__ __forceinline__ uint32_t pack4_e4m3(float4 v) {
    uint16_t lo, hi;
    asm("cvt.rn.satfinite.e4m3x2.f32 %0, %1, %2;" : "=h"(lo) : "f"(v.y), "f"(v.x));
    asm("cvt.rn.satfinite.e4m3x2.f32 %0, %1, %2;" : "=h"(hi) : "f"(v.w), "f"(v.z));
    return (uint32_t)lo | ((uint32_t)hi << 16);
}

// merged prep: blocks 0-47 convert W, blocks 48+ convert value_vocab
__global__ void prep_kernel(const float* __restrict__ W,
                            const float* __restrict__ vv) {
    if (blockIdx.x < 48) {
        int i = blockIdx.x * 256 + threadIdx.x;      // 0..12287 (128 rows x 96 quads)
        int d = i / 96, j = i % 96;
        float4 v = ((const float4*)W)[i];
        *(uint32_t*)(g_Wf8 + d * CTX_BSTRIDE + j * 4) = pack4_e4m3(v);
    } else {
        size_t q0 = ((size_t)(blockIdx.x - 48) * 256 + threadIdx.x) * 4;
        uint32_t o[4];
#pragma unroll
        for (int u = 0; u < 4; u++)
            o[u] = pack4_e4m3(((const float4*)vv)[q0 + u]);
        *(uint4*)(g_valf8 + q0 * 4) = make_uint4(o[0], o[1], o[2], o[3]);
    }
}

__device__ __forceinline__ float fast_tanhf(float x) {
    float y; asm("tanh.approx.f32 %0, %1;" : "=f"(y) : "f"(x)); return y;
}
__device__ __forceinline__ void mma_f8(float* acc, uint32_t a0, uint32_t a1,
                                       uint32_t a2, uint32_t a3,
                                       uint32_t b0, uint32_t b1) {
    asm volatile(
        "mma.sync.aligned.m16n8k32.row.col.f32.e4m3.e4m3.f32 "
        "{%0,%1,%2,%3},{%4,%5,%6,%7},{%8,%9},{%0,%1,%2,%3};"
        : "+f"(acc[0]), "+f"(acc[1]), "+f"(acc[2]), "+f"(acc[3])
        : "r"(a0), "r"(a1), "r"(a2), "r"(a3), "r"(b0), "r"(b1));
}
__device__ __forceinline__ void ldsm_x4(uint32_t& r0, uint32_t& r1,
                                        uint32_t& r2, uint32_t& r3, uint32_t saddr) {
    asm volatile("ldmatrix.sync.aligned.m8n8.x4.shared.b16 {%0,%1,%2,%3}, [%4];"
                 : "=r"(r0), "=r"(r1), "=r"(r2), "=r"(r3) : "r"(saddr));
}
__device__ __forceinline__ float4 ldg_nc_v4(const float* p) {
    float4 r;
    asm volatile("ld.global.nc.v4.f32 {%0,%1,%2,%3}, [%4];"
                 : "=f"(r.x), "=f"(r.y), "=f"(r.z), "=f"(r.w) : "l"(p));
    return r;
}
__device__ __forceinline__ uint4 ldg_nc_u4(const void* p) {
    uint4 r;
    asm volatile("ld.global.nc.v4.b32 {%0,%1,%2,%3}, [%4];"
                 : "=r"(r.x), "=r"(r.y), "=r"(r.z), "=r"(r.w) : "l"(p));
    return r;
}

__global__ void __launch_bounds__(THREADS, 2)
acv_fused_kernel(const int* __restrict__ xs_xt,
                 const int* __restrict__ path_idx,
                 const float* __restrict__ path_vocab,
                 const float* __restrict__ att_vec,
                 const float* __restrict__ dense_w,
                 const float* __restrict__ dense_b,
                 float* __restrict__ out)
{
    extern __shared__ unsigned char smem[];
    uint64_t* vsp = (uint64_t*)(smem + OFF_PTR);         // xs value-row ptrs
    uint64_t* vpp = vsp + 256;                           // path row ptrs
    uint64_t* vtp = vpp + 256;                           // xt value-row ptrs
    float* avs   = (float*)(smem + OFF_AV);
    float* sp    = (float*)(smem + OFF_SP);
    float* esc   = (float*)(smem + OFF_ESC);
    float* codep = (float*)(smem + OFF_CODEP);
    float* codes = (float*)(smem + OFF_CODES);
    float* zs    = (float*)(smem + OFF_ZS);
    float* ep    = (float*)(smem + OFF_EP);

    const int tid  = threadIdx.x;
    const int b    = blockIdx.x;
    const int lane = tid & 31;
    const int warp = tid >> 5;

    // ---- cp.async W (pre-converted fp8) into smem ----
    {
        uint32_t ws = (uint32_t)__cvta_generic_to_shared(smem + OFF_W);
        const char* wg = (const char*)g_Wf8;
        for (int i = tid; i < SZ_W / 16; i += THREADS)
            asm volatile("cp.async.cg.shared.global [%0], [%1], 16;"
                         :: "r"(ws + i * 16), "l"(wg + i * 16));
        asm volatile("cp.async.commit_group;");
    }

    // ---- stage row pointers (padded to 256 rows) ----
    for (int i = tid; i < 2 * NCTX; i += THREADS) {
        int v = xs_xt[b * 2 * NCTX + i];
        uint64_t p = (uint64_t)(g_valf8 + (size_t)v * 128);
        if (i & 1) vtp[i >> 1] = p; else vsp[i >> 1] = p;
    }
    if (tid < NCTX)
        vpp[tid] = (uint64_t)(path_vocab + (size_t)path_idx[b * NCTX + tid] * 128);
    if (tid < 56) {
        vsp[NCTX + tid] = (uint64_t)g_valf8;
        vpp[NCTX + tid] = (uint64_t)path_vocab;
        vtp[NCTX + tid] = (uint64_t)g_valf8;
    }
    if (tid < D) avs[tid] = att_vec[tid];
    asm volatile("cp.async.wait_group 0;");
    __syncthreads();

    // ---- warp tiling: 2 m-warps (32 rows) x 8 n-warps (16 cols), m32n16 per warp ----
    const int mwarp = warp & 1;
    const int nwarp = warp >> 1;
    const int g  = lane >> 2;
    const int tg = lane & 3;

    const uint32_t ctx_s = (uint32_t)__cvta_generic_to_shared(smem + OFF_CTX);
    const uint32_t w_s   = (uint32_t)__cvta_generic_to_shared(smem + OFF_W);

    const uint32_t a_off0 = (uint32_t)((mwarp * 32 + (lane & 15)) * CTX_BSTRIDE + (lane >> 4) * 16);
    const uint32_t a_off1 = a_off0 + 16 * CTX_BSTRIDE;
    const int bc = ((lane >> 4) << 3) + (lane & 7);
    const uint32_t b_off = (uint32_t)((nwarp * 16 + bc) * CTX_BSTRIDE + ((lane >> 3) & 1) * 16);

    float av4[4];
#pragma unroll
    for (int jj = 0; jj < 2; jj++) {
        int col = nwarp * 16 + jj * 8 + tg * 2;
        av4[jj * 2]     = avs[col];
        av4[jj * 2 + 1] = avs[col + 1];
    }

    // gather role: 8 threads per row
    const int grow = tid >> 3;     // row within tile (0..63)
    const int gsub = tid & 7;

    float cpart[4] = {0.f, 0.f, 0.f, 0.f};
    float resum = 0.f;

    for (int t = 0; t < NTILES; t++) {
        const int n0 = t * TILE_N;

        // ---- gather tile t: per thread = 1 row, 1/8 of its 3 segments ----
        {
            const int gr = n0 + grow;
            const char* ps = (const char*)vsp[gr];
            const char* pp = (const char*)vpp[gr];
            const char* pt = (const char*)vtp[gr];
            uint4 vx  = ldg_nc_u4(ps + gsub * 16);
            uint4 vt2 = ldg_nc_u4(pt + gsub * 16);
            float4 f0 = ldg_nc_v4((const float*)pp + (gsub)      * 4);
            float4 f1 = ldg_nc_v4((const float*)pp + (gsub + 8)  * 4);
            float4 f2 = ldg_nc_v4((const float*)pp + (gsub + 16) * 4);
            float4 f3 = ldg_nc_v4((const float*)pp + (gsub + 24) * 4);
            unsigned char* crow = smem + OFF_CTX + grow * CTX_BSTRIDE;
            *(uint4*)(crow + gsub * 16)       = vx;
            *(uint4*)(crow + 256 + gsub * 16) = vt2;
            *(uint32_t*)(crow + 128 + (gsub)      * 4) = pack4_e4m3(f0);
            *(uint32_t*)(crow + 128 + (gsub + 8)  * 4) = pack4_e4m3(f1);
            *(uint32_t*)(crow + 128 + (gsub + 16) * 4) = pack4_e4m3(f2);
            *(uint32_t*)(crow + 128 + (gsub + 24) * 4) = pack4_e4m3(f3);
        }
        __syncthreads();

        // ---- GEMM: acc[m][jj][c], 12 k32-steps ----
        float acc[2][2][4];
#pragma unroll
        for (int m = 0; m < 2; m++)
#pragma unroll
            for (int jj = 0; jj < 2; jj++)
#pragma unroll
                for (int c = 0; c < 4; c++) acc[m][jj][c] = 0.f;

        if (t < NTILES - 1) {
            // full 64-row tile
#pragma unroll
            for (int kk = 0; kk < 12; kk++) {
                uint32_t a[2][4], bq[4];
                ldsm_x4(a[0][0], a[0][1], a[0][2], a[0][3], ctx_s + a_off0 + kk * 32);
                ldsm_x4(a[1][0], a[1][1], a[1][2], a[1][3], ctx_s + a_off1 + kk * 32);
                ldsm_x4(bq[0], bq[1], bq[2], bq[3], w_s + b_off + kk * 32);
#pragma unroll
                for (int m = 0; m < 2; m++) {
                    mma_f8(acc[m][0], a[m][0], a[m][1], a[m][2], a[m][3], bq[0], bq[1]);
                    mma_f8(acc[m][1], a[m][0], a[m][1], a[m][2], a[m][3], bq[2], bq[3]);
                }
            }
        } else if (mwarp == 0) {
            // tail tile: only rows 0-7 valid (NCTX=200=3*64+8) -> m=0 strip of
            // mwarp==0 warps only. Stale acc elsewhere is neutralized by esc=0.
#pragma unroll
            for (int kk = 0; kk < 12; kk++) {
                uint32_t a0[4], bq[4];
                ldsm_x4(a0[0], a0[1], a0[2], a0[3], ctx_s + a_off0 + kk * 32);
                ldsm_x4(bq[0], bq[1], bq[2], bq[3], w_s + b_off + kk * 32);
                mma_f8(acc[0][0], a0[0], a0[1], a0[2], a0[3], bq[0], bq[1]);
                mma_f8(acc[0][1], a0[0], a0[1], a0[2], a0[3], bq[2], bq[3]);
            }
        }

        // ---- tanh in place + score partials ----
#pragma unroll
        for (int m = 0; m < 2; m++)
#pragma unroll
            for (int jj = 0; jj < 2; jj++)
#pragma unroll
                for (int c = 0; c < 4; c++)
                    acc[m][jj][c] = fast_tanhf(acc[m][jj][c]);

#pragma unroll
        for (int m = 0; m < 2; m++) {
#pragma unroll
            for (int h = 0; h < 2; h++) {
                float p = 0.f;
#pragma unroll
                for (int jj = 0; jj < 2; jj++) {
                    p += av4[jj * 2]     * acc[m][jj][h * 2];
                    p += av4[jj * 2 + 1] * acc[m][jj][h * 2 + 1];
                }
                p += __shfl_xor_sync(0xFFFFFFFFu, p, 1);
                p += __shfl_xor_sync(0xFFFFFFFFu, p, 2);
                if (tg == 0) {
                    int row = mwarp * 32 + m * 16 + h * 8 + g;
                    sp[row * 8 + nwarp] = p;
                }
            }
        }
        __syncthreads();

        if (tid < TILE_N) {
            float s = 0.f;
#pragma unroll
            for (int w8 = 0; w8 < 8; w8++) s += sp[tid * 8 + w8];
            float e = (n0 + tid < NCTX) ? __expf(s) : 0.f;
            esc[tid] = e;
            resum += e;
        }
        __syncthreads();

        // ---- weighted accumulation from registers ----
#pragma unroll
        for (int m = 0; m < 2; m++) {
#pragma unroll
            for (int h = 0; h < 2; h++) {
                float e = esc[mwarp * 32 + m * 16 + h * 8 + g];
#pragma unroll
                for (int jj = 0; jj < 2; jj++) {
                    cpart[jj * 2]     += e * acc[m][jj][h * 2];
                    cpart[jj * 2 + 1] += e * acc[m][jj][h * 2 + 1];
                }
            }
        }
        // next gather may overwrite ctx: all warps passed GEMM (sp-sync above).
    }

    // ---- reduce cpart across g, write per-mwarp col partials ----
#pragma unroll
    for (int off = 4; off < 32; off <<= 1)
#pragma unroll
        for (int i = 0; i < 4; i++)
            cpart[i] += __shfl_xor_sync(0xFFFFFFFFu, cpart[i], off);
    if (g == 0) {
#pragma unroll
        for (int jj = 0; jj < 2; jj++) {
            int col = nwarp * 16 + jj * 8 + tg * 2;
            codep[col * 2 + mwarp]       = cpart[jj * 2];
            codep[(col + 1) * 2 + mwarp] = cpart[jj * 2 + 1];
        }
    }
    if (tid < TILE_N) {
        float s = resum;
#pragma unroll
        for (int off = 16; off > 0; off >>= 1)
            s += __shfl_xor_sync(0xFFFFFFFFu, s, off);
        if (lane == 0) ep[warp] = s;
    }
    __syncthreads();

    float esum = ep[0] + ep[1];
    if (tid < D) {
        float c = codep[tid * 2] + codep[tid * 2 + 1];
        codes[tid] = c / esum;
    }
    __syncthreads();

    // ---- dense + sigmoid ----
    {
        const int grp = tid >> 7, dcol = tid & 127;
        float z = 0.f;
#pragma unroll 8
        for (int d2 = 0; d2 < 32; d2++) {
            int d = grp * 32 + d2;
            z += codes[d] * dense_w[d * OUTD + dcol];
        }
        if (grp != 0) zs[(grp - 1) * 128 + dcol] = z;
        __syncthreads();
        if (grp == 0) {
            float zz = z + zs[dcol] + zs[128 + dcol] + zs[256 + dcol] + dense_b[dcol];
            out[b * OUTD + dcol] = 1.f / (1.f + __expf(-zz));
        }
    }
}

extern "C" void kernel_launch(void* const* d_in, const int* in_sizes, int n_in,
                              void* d_out, int out_size)
{
    const int*   xs_xt       = (const int*)d_in[0];
    const int*   path_idx    = (const int*)d_in[1];
    const float* value_vocab = (const float*)d_in[2];
    const float* path_vocab  = (const float*)d_in[3];
    const float* W           = (const float*)d_in[4];
    const float* att_vec     = (const float*)d_in[5];
    const float* dense_w     = (const float*)d_in[6];
    const float* dense_b     = (const float*)d_in[7];
    float*       out         = (float*)d_out;

    prep_kernel<<<48 + 3125, 256>>>(W, value_vocab);

    cudaFuncSetAttribute(acv_fused_kernel,
                         cudaFuncAttributeMaxDynamicSharedMemorySize, SMEM_BYTES);
    acv_fused_kernel<<<1024, THREADS, SMEM_BYTES>>>(
        xs_xt, path_idx, path_vocab, att_vec,
        dense_w, dense_b, out);
}

// round 13
// speedup vs baseline: 1.3444x; 1.0064x over previous
#include <cuda_runtime.h>
#include <cuda_bf16.h>
#include <stdint.h>

// Problem constants
#define VALUE_VOCAB 100000
#define NCTX      200
#define D         128
#define F         384
#define OUTD      128
#define THREADS   512
#define TILE_N    64
#define NTILES    4            // 4 x 64 = 256 rows (padded; invalid rows esc=0)
#define TAIL_ROWS 8            // NCTX - 3*64

#define CTX_BSTRIDE  400       // bytes per ctx/W row (384 fp8 + 16 pad)

// ---- smem layout (bytes) ----
#define OFF_W      0
#define SZ_W       (D * CTX_BSTRIDE)              // 51200
#define OFF_CTX    (OFF_W + SZ_W)                 // 51200
#define SZ_CTX     (TILE_N * CTX_BSTRIDE)         // 25600
#define OFF_PTR    (OFF_CTX + SZ_CTX)             // 76800 : 3*256*8 = 6144
#define OFF_AV     (OFF_PTR + 6144)               // 512
#define OFF_SP     (OFF_AV + 512)                 // 2048
#define OFF_ESC    (OFF_SP + 2048)                // 256
#define OFF_CODEP  (OFF_ESC + 256)                // 1024
#define OFF_CODES  (OFF_CODEP + 1024)             // 512
#define OFF_ZS     (OFF_CODES + 512)              // 1536
#define OFF_EP     (OFF_ZS + 1536)                // 64
#define SMEM_BYTES (OFF_EP + 64)                  // ~88.6 KB (2 CTAs/SM)

// W pre-converted to e4m3, row stride 400 B
__device__ __align__(16) unsigned char g_Wf8[SZ_W];
// value_vocab pre-converted to e4m3, rows of 128 B
__device__ __align__(16) unsigned char g_valf8[(size_t)VALUE_VOCAB * 128];

__device__ __forceinline__ uint32_t pack4_e4m3(float4 v) {
    uint16_t lo, hi;
    asm("cvt.rn.satfinite.e4m3x2.f32 %0, %1, %2;" : "=h"(lo) : "f"(v.y), "f"(v.x));
    asm("cvt.rn.satfinite.e4m3x2.f32 %0, %1, %2;" : "=h"(hi) : "f"(v.w), "f"(v.z));
    return (uint32_t)lo | ((uint32_t)hi << 16);
}

// merged prep (512-thread blocks): blocks 0-23 convert W, blocks 24+ convert value_vocab
__global__ void prep_kernel(const float* __restrict__ W,
                            const float* __restrict__ vv) {
    if (blockIdx.x < 24) {
        int i = blockIdx.x * 512 + threadIdx.x;      // 0..12287 (128 rows x 96 quads)
        int d = i / 96, j = i % 96;
        float4 v = ((const float4*)W)[i];
        *(uint32_t*)(g_Wf8 + d * CTX_BSTRIDE + j * 4) = pack4_e4m3(v);
    } else {
        size_t idx = (size_t)(blockIdx.x - 24) * 512 + threadIdx.x;
        if (idx < 800000) {                          // 3.2M quads / 4 per thread
            size_t q0 = idx * 4;
            uint32_t o[4];
#pragma unroll
            for (int u = 0; u < 4; u++)
                o[u] = pack4_e4m3(((const float4*)vv)[q0 + u]);
            *(uint4*)(g_valf8 + q0 * 4) = make_uint4(o[0], o[1], o[2], o[3]);
        }
    }
}

__device__ __forceinline__ float fast_tanhf(float x) {
    float y; asm("tanh.approx.f32 %0, %1;" : "=f"(y) : "f"(x)); return y;
}
__device__ __forceinline__ void mma_f8(float* acc, uint32_t a0, uint32_t a1,
                                       uint32_t a2, uint32_t a3,
                                       uint32_t b0, uint32_t b1) {
    asm volatile(
        "mma.sync.aligned.m16n8k32.row.col.f32.e4m3.e4m3.f32 "
        "{%0,%1,%2,%3},{%4,%5,%6,%7},{%8,%9},{%0,%1,%2,%3};"
        : "+f"(acc[0]), "+f"(acc[1]), "+f"(acc[2]), "+f"(acc[3])
        : "r"(a0), "r"(a1), "r"(a2), "r"(a3), "r"(b0), "r"(b1));
}
__device__ __forceinline__ void ldsm_x4(uint32_t& r0, uint32_t& r1,
                                        uint32_t& r2, uint32_t& r3, uint32_t saddr) {
    asm volatile("ldmatrix.sync.aligned.m8n8.x4.shared.b16 {%0,%1,%2,%3}, [%4];"
                 : "=r"(r0), "=r"(r1), "=r"(r2), "=r"(r3) : "r"(saddr));
}
__device__ __forceinline__ float4 ldg_nc_v4(const float* p) {
    float4 r;
    asm volatile("ld.global.nc.v4.f32 {%0,%1,%2,%3}, [%4];"
                 : "=f"(r.x), "=f"(r.y), "=f"(r.z), "=f"(r.w) : "l"(p));
    return r;
}
__device__ __forceinline__ uint4 ldg_nc_u4(const void* p) {
    uint4 r;
    asm volatile("ld.global.nc.v4.b32 {%0,%1,%2,%3}, [%4];"
                 : "=r"(r.x), "=r"(r.y), "=r"(r.z), "=r"(r.w) : "l"(p));
    return r;
}

__global__ void __launch_bounds__(THREADS, 2)
acv_fused_kernel(const int* __restrict__ xs_xt,
                 const int* __restrict__ path_idx,
                 const float* __restrict__ path_vocab,
                 const float* __restrict__ att_vec,
                 const float* __restrict__ dense_w,
                 const float* __restrict__ dense_b,
                 float* __restrict__ out)
{
    extern __shared__ unsigned char smem[];
    uint64_t* vsp = (uint64_t*)(smem + OFF_PTR);         // xs value-row ptrs
    uint64_t* vpp = vsp + 256;                           // path row ptrs
    uint64_t* vtp = vpp + 256;                           // xt value-row ptrs
    float* avs   = (float*)(smem + OFF_AV);
    float* sp    = (float*)(smem + OFF_SP);
    float* esc   = (float*)(smem + OFF_ESC);
    float* codep = (float*)(smem + OFF_CODEP);
    float* codes = (float*)(smem + OFF_CODES);
    float* zs    = (float*)(smem + OFF_ZS);
    float* ep    = (float*)(smem + OFF_EP);

    const int tid  = threadIdx.x;
    const int b    = blockIdx.x;
    const int lane = tid & 31;
    const int warp = tid >> 5;

    // ---- cp.async W (pre-converted fp8) into smem ----
    {
        uint32_t ws = (uint32_t)__cvta_generic_to_shared(smem + OFF_W);
        const char* wg = (const char*)g_Wf8;
        for (int i = tid; i < SZ_W / 16; i += THREADS)
            asm volatile("cp.async.cg.shared.global [%0], [%1], 16;"
                         :: "r"(ws + i * 16), "l"(wg + i * 16));
        asm volatile("cp.async.commit_group;");
    }

    // ---- stage row pointers (padded to 256 rows) ----
    for (int i = tid; i < 2 * NCTX; i += THREADS) {
        int v = xs_xt[b * 2 * NCTX + i];
        uint64_t p = (uint64_t)(g_valf8 + (size_t)v * 128);
        if (i & 1) vtp[i >> 1] = p; else vsp[i >> 1] = p;
    }
    if (tid < NCTX)
        vpp[tid] = (uint64_t)(path_vocab + (size_t)path_idx[b * NCTX + tid] * 128);
    if (tid < 56) {
        vsp[NCTX + tid] = (uint64_t)g_valf8;
        vpp[NCTX + tid] = (uint64_t)path_vocab;
        vtp[NCTX + tid] = (uint64_t)g_valf8;
    }
    if (tid < D) avs[tid] = att_vec[tid];
    asm volatile("cp.async.wait_group 0;");
    __syncthreads();

    // ---- warp tiling: 2 m-warps (32 rows) x 8 n-warps (16 cols), m32n16 per warp ----
    const int mwarp = warp & 1;
    const int nwarp = warp >> 1;
    const int g  = lane >> 2;
    const int tg = lane & 3;

    const uint32_t ctx_s = (uint32_t)__cvta_generic_to_shared(smem + OFF_CTX);
    const uint32_t w_s   = (uint32_t)__cvta_generic_to_shared(smem + OFF_W);

    const uint32_t a_off0 = (uint32_t)((mwarp * 32 + (lane & 15)) * CTX_BSTRIDE + (lane >> 4) * 16);
    const uint32_t a_off1 = a_off0 + 16 * CTX_BSTRIDE;
    const int bc = ((lane >> 4) << 3) + (lane & 7);
    const uint32_t b_off = (uint32_t)((nwarp * 16 + bc) * CTX_BSTRIDE + ((lane >> 3) & 1) * 16);

    float av4[4];
#pragma unroll
    for (int jj = 0; jj < 2; jj++) {
        int col = nwarp * 16 + jj * 8 + tg * 2;
        av4[jj * 2]     = avs[col];
        av4[jj * 2 + 1] = avs[col + 1];
    }

    // gather role: 8 threads per row
    const int grow = tid >> 3;     // row within tile (0..63)
    const int gsub = tid & 7;

    float cpart[4] = {0.f, 0.f, 0.f, 0.f};
    float resum = 0.f;

    for (int t = 0; t < NTILES; t++) {
        const int n0 = t * TILE_N;
        const bool full = (t < NTILES - 1);

        // ---- gather tile t (tail: only rows < TAIL_ROWS are needed) ----
        if (full || grow < TAIL_ROWS) {
            const int gr = n0 + grow;
            const char* ps = (const char*)vsp[gr];
            const char* pp = (const char*)vpp[gr];
            const char* pt = (const char*)vtp[gr];
            uint4 vx  = ldg_nc_u4(ps + gsub * 16);
            uint4 vt2 = ldg_nc_u4(pt + gsub * 16);
            float4 f0 = ldg_nc_v4((const float*)pp + (gsub)      * 4);
            float4 f1 = ldg_nc_v4((const float*)pp + (gsub + 8)  * 4);
            float4 f2 = ldg_nc_v4((const float*)pp + (gsub + 16) * 4);
            float4 f3 = ldg_nc_v4((const float*)pp + (gsub + 24) * 4);
            unsigned char* crow = smem + OFF_CTX + grow * CTX_BSTRIDE;
            *(uint4*)(crow + gsub * 16)       = vx;
            *(uint4*)(crow + 256 + gsub * 16) = vt2;
            *(uint32_t*)(crow + 128 + (gsub)      * 4) = pack4_e4m3(f0);
            *(uint32_t*)(crow + 128 + (gsub + 8)  * 4) = pack4_e4m3(f1);
            *(uint32_t*)(crow + 128 + (gsub + 16) * 4) = pack4_e4m3(f2);
            *(uint32_t*)(crow + 128 + (gsub + 24) * 4) = pack4_e4m3(f3);
        }
        __syncthreads();

        // ---- GEMM: acc[m][jj][c], 12 k32-steps ----
        float acc[2][2][4];
#pragma unroll
        for (int m = 0; m < 2; m++)
#pragma unroll
            for (int jj = 0; jj < 2; jj++)
#pragma unroll
                for (int c = 0; c < 4; c++) acc[m][jj][c] = 0.f;

        if (full) {
#pragma unroll
            for (int kk = 0; kk < 12; kk++) {
                uint32_t a[2][4], bq[4];
                ldsm_x4(a[0][0], a[0][1], a[0][2], a[0][3], ctx_s + a_off0 + kk * 32);
                ldsm_x4(a[1][0], a[1][1], a[1][2], a[1][3], ctx_s + a_off1 + kk * 32);
                ldsm_x4(bq[0], bq[1], bq[2], bq[3], w_s + b_off + kk * 32);
#pragma unroll
                for (int m = 0; m < 2; m++) {
                    mma_f8(acc[m][0], a[m][0], a[m][1], a[m][2], a[m][3], bq[0], bq[1]);
                    mma_f8(acc[m][1], a[m][0], a[m][1], a[m][2], a[m][3], bq[2], bq[3]);
                }
            }
        } else if (mwarp == 0) {
            // tail: only rows 0-7 valid -> m=0 strip of mwarp==0 warps.
            // Stale ctx/acc elsewhere neutralized by esc=0.
#pragma unroll
            for (int kk = 0; kk < 12; kk++) {
                uint32_t a0[4], bq[4];
                ldsm_x4(a0[0], a0[1], a0[2], a0[3], ctx_s + a_off0 + kk * 32);
                ldsm_x4(bq[0], bq[1], bq[2], bq[3], w_s + b_off + kk * 32);
                mma_f8(acc[0][0], a0[0], a0[1], a0[2], a0[3], bq[0], bq[1]);
                mma_f8(acc[0][1], a0[0], a0[1], a0[2], a0[3], bq[2], bq[3]);
            }
        }

        // ---- tanh in place + score partials (tail: mwarp==0 only) ----
        if (full || mwarp == 0) {
#pragma unroll
            for (int m = 0; m < 2; m++)
#pragma unroll
                for (int jj = 0; jj < 2; jj++)
#pragma unroll
                    for (int c = 0; c < 4; c++)
                        acc[m][jj][c] = fast_tanhf(acc[m][jj][c]);

#pragma unroll
            for (int m = 0; m < 2; m++) {
#pragma unroll
                for (int h = 0; h < 2; h++) {
                    float p = 0.f;
#pragma unroll
                    for (int jj = 0; jj < 2; jj++) {
                        p += av4[jj * 2]     * acc[m][jj][h * 2];
                        p += av4[jj * 2 + 1] * acc[m][jj][h * 2 + 1];
                    }
                    p += __shfl_xor_sync(0xFFFFFFFFu, p, 1);
                    p += __shfl_xor_sync(0xFFFFFFFFu, p, 2);
                    if (tg == 0) {
                        int row = mwarp * 32 + m * 16 + h * 8 + g;
                        sp[row * 8 + nwarp] = p;
                    }
                }
            }
        }
        __syncthreads();

        if (tid < TILE_N) {
            float4 s0 = *(const float4*)&sp[tid * 8];
            float4 s1 = *(const float4*)&sp[tid * 8 + 4];
            float s = (s0.x + s0.y) + (s0.z + s0.w) + (s1.x + s1.y) + (s1.z + s1.w);
            float e;
            if (full) e = __expf(s);                       // n0+tid < 200 always
            else      e = (tid < TAIL_ROWS) ? __expf(s) : 0.f;
            esc[tid] = e;
            resum += e;
        }
        __syncthreads();

        // ---- weighted accumulation from registers (tail: mwarp==0 only) ----
        if (full || mwarp == 0) {
#pragma unroll
            for (int m = 0; m < 2; m++) {
#pragma unroll
                for (int h = 0; h < 2; h++) {
                    float e = esc[mwarp * 32 + m * 16 + h * 8 + g];
#pragma unroll
                    for (int jj = 0; jj < 2; jj++) {
                        cpart[jj * 2]     += e * acc[m][jj][h * 2];
                        cpart[jj * 2 + 1] += e * acc[m][jj][h * 2 + 1];
                    }
                }
            }
        }
        // next gather may overwrite ctx: all warps passed GEMM (sp-sync above).
    }

    // ---- reduce cpart across g, write per-mwarp col partials ----
#pragma unroll
    for (int off = 4; off < 32; off <<= 1)
#pragma unroll
        for (int i = 0; i < 4; i++)
            cpart[i] += __shfl_xor_sync(0xFFFFFFFFu, cpart[i], off);
    if (g == 0) {
#pragma unroll
        for (int jj = 0; jj < 2; jj++) {
            int col = nwarp * 16 + jj * 8 + tg * 2;
            codep[col * 2 + mwarp]       = cpart[jj * 2];
            codep[(col + 1) * 2 + mwarp] = cpart[jj * 2 + 1];
        }
    }
    if (tid < TILE_N) {
        float s = resum;
#pragma unroll
        for (int off = 16; off > 0; off >>= 1)
            s += __shfl_xor_sync(0xFFFFFFFFu, s, off);
        if (lane == 0) ep[warp] = s;
    }
    __syncthreads();

    float esum = ep[0] + ep[1];
    if (tid < D) {
        float c = codep[tid * 2] + codep[tid * 2 + 1];
        codes[tid] = c / esum;
    }
    __syncthreads();

    // ---- dense + sigmoid ----
    {
        const int grp = tid >> 7, dcol = tid & 127;
        float z = 0.f;
#pragma unroll 8
        for (int d2 = 0; d2 < 32; d2++) {
            int d = grp * 32 + d2;
            z += codes[d] * dense_w[d * OUTD + dcol];
        }
        if (grp != 0) zs[(grp - 1) * 128 + dcol] = z;
        __syncthreads();
        if (grp == 0) {
            float zz = z + zs[dcol] + zs[128 + dcol] + zs[256 + dcol] + dense_b[dcol];
            out[b * OUTD + dcol] = 1.f / (1.f + __expf(-zz));
        }
    }
}

extern "C" void kernel_launch(void* const* d_in, const int* in_sizes, int n_in,
                              void* d_out, int out_size)
{
    const int*   xs_xt       = (const int*)d_in[0];
    const int*   path_idx    = (const int*)d_in[1];
    const float* value_vocab = (const float*)d_in[2];
    const float* path_vocab  = (const float*)d_in[3];
    const float* W           = (const float*)d_in[4];
    const float* att_vec     = (const float*)d_in[5];
    const float* dense_w     = (const float*)d_in[6];
    const float* dense_b     = (const float*)d_in[7];
    float*       out         = (float*)d_out;

    prep_kernel<<<24 + 1563, 512>>>(W, value_vocab);

    cudaFuncSetAttribute(acv_fused_kernel,
                         cudaFuncAttributeMaxDynamicSharedMemorySize, SMEM_BYTES);
    acv_fused_kernel<<<1024, THREADS, SMEM_BYTES>>>(
        xs_xt, path_idx, path_vocab, att_vec,
        dense_w, dense_b, out);
}

// round 14
// speedup vs baseline: 1.3451x; 1.0006x over previous
#include <cuda_runtime.h>
#include <cuda_bf16.h>
#include <stdint.h>

// Problem constants
#define VALUE_VOCAB 100000
#define NCTX      200
#define D         128
#define F         384
#define OUTD      128
#define THREADS   512
#define TILE_N    64
#define NTILES    4            // 4 x 64 = 256 rows (padded; invalid rows esc=0)
#define TAIL_ROWS 8            // NCTX - 3*64

#define CTX_BSTRIDE  400       // bytes per ctx/W row (384 fp8 + 16 pad)

// ---- smem layout (bytes) ----
#define OFF_W      0
#define SZ_W       (D * CTX_BSTRIDE)              // 51200
#define OFF_CTX    (OFF_W + SZ_W)                 // 51200
#define SZ_CTX     (TILE_N * CTX_BSTRIDE)         // 25600
#define OFF_PTR    (OFF_CTX + SZ_CTX)             // 76800 : 3*256*8 = 6144
#define OFF_AV     (OFF_PTR + 6144)               // 512
#define OFF_SP     (OFF_AV + 512)                 // 2048
#define OFF_ESC    (OFF_SP + 2048)                // 256
#define OFF_CODEP  (OFF_ESC + 256)                // 1024
#define OFF_CODES  (OFF_CODEP + 1024)             // 512
#define OFF_ZS     (OFF_CODES + 512)              // 1536
#define OFF_EP     (OFF_ZS + 1536)                // 64
#define SMEM_BYTES (OFF_EP + 64)                  // ~88.6 KB (2 CTAs/SM)

// W pre-converted to e4m3, row stride 400 B
__device__ __align__(16) unsigned char g_Wf8[SZ_W];
// value_vocab pre-converted to e4m3, rows of 128 B
__device__ __align__(16) unsigned char g_valf8[(size_t)VALUE_VOCAB * 128];

__device__ __forceinline__ uint32_t pack4_e4m3(float4 v) {
    uint16_t lo, hi;
    asm("cvt.rn.satfinite.e4m3x2.f32 %0, %1, %2;" : "=h"(lo) : "f"(v.y), "f"(v.x));
    asm("cvt.rn.satfinite.e4m3x2.f32 %0, %1, %2;" : "=h"(hi) : "f"(v.w), "f"(v.z));
    return (uint32_t)lo | ((uint32_t)hi << 16);
}

// merged prep (512-thread blocks): blocks 0-23 convert W, blocks 24+ convert value_vocab
__global__ void prep_kernel(const float* __restrict__ W,
                            const float* __restrict__ vv) {
    if (blockIdx.x < 24) {
        int i = blockIdx.x * 512 + threadIdx.x;      // 0..12287 (128 rows x 96 quads)
        int d = i / 96, j = i % 96;
        float4 v = ((const float4*)W)[i];
        *(uint32_t*)(g_Wf8 + d * CTX_BSTRIDE + j * 4) = pack4_e4m3(v);
    } else {
        size_t idx = (size_t)(blockIdx.x - 24) * 512 + threadIdx.x;
        if (idx < 800000) {                          // 3.2M quads / 4 per thread
            size_t q0 = idx * 4;
            uint32_t o[4];
#pragma unroll
            for (int u = 0; u < 4; u++)
                o[u] = pack4_e4m3(((const float4*)vv)[q0 + u]);
            *(uint4*)(g_valf8 + q0 * 4) = make_uint4(o[0], o[1], o[2], o[3]);
        }
    }
}

__device__ __forceinline__ float fast_tanhf(float x) {
    float y; asm("tanh.approx.f32 %0, %1;" : "=f"(y) : "f"(x)); return y;
}
__device__ __forceinline__ void mma_f8(float* acc, uint32_t a0, uint32_t a1,
                                       uint32_t a2, uint32_t a3,
                                       uint32_t b0, uint32_t b1) {
    asm volatile(
        "mma.sync.aligned.m16n8k32.row.col.f32.e4m3.e4m3.f32 "
        "{%0,%1,%2,%3},{%4,%5,%6,%7},{%8,%9},{%0,%1,%2,%3};"
        : "+f"(acc[0]), "+f"(acc[1]), "+f"(acc[2]), "+f"(acc[3])
        : "r"(a0), "r"(a1), "r"(a2), "r"(a3), "r"(b0), "r"(b1));
}
__device__ __forceinline__ void ldsm_x4(uint32_t& r0, uint32_t& r1,
                                        uint32_t& r2, uint32_t& r3, uint32_t saddr) {
    asm volatile("ldmatrix.sync.aligned.m8n8.x4.shared.b16 {%0,%1,%2,%3}, [%4];"
                 : "=r"(r0), "=r"(r1), "=r"(r2), "=r"(r3) : "r"(saddr));
}
__device__ __forceinline__ float4 ldg_nc_v4(const float* p) {
    float4 r;
    asm volatile("ld.global.nc.v4.f32 {%0,%1,%2,%3}, [%4];"
                 : "=f"(r.x), "=f"(r.y), "=f"(r.z), "=f"(r.w) : "l"(p));
    return r;
}
__device__ __forceinline__ uint4 ldg_nc_u4(const void* p) {
    uint4 r;
    asm volatile("ld.global.nc.v4.b32 {%0,%1,%2,%3}, [%4];"
                 : "=r"(r.x), "=r"(r.y), "=r"(r.z), "=r"(r.w) : "l"(p));
    return r;
}

__global__ void __launch_bounds__(THREADS, 2)
acv_fused_kernel(const int* __restrict__ xs_xt,
                 const int* __restrict__ path_idx,
                 const float* __restrict__ path_vocab,
                 const float* __restrict__ att_vec,
                 const float* __restrict__ dense_w,
                 const float* __restrict__ dense_b,
                 float* __restrict__ out)
{
    extern __shared__ unsigned char smem[];
    uint64_t* vsp = (uint64_t*)(smem + OFF_PTR);         // xs value-row ptrs
    uint64_t* vpp = vsp + 256;                           // path row ptrs
    uint64_t* vtp = vpp + 256;                           // xt value-row ptrs
    float* avs   = (float*)(smem + OFF_AV);
    float* sp    = (float*)(smem + OFF_SP);
    float* esc   = (float*)(smem + OFF_ESC);
    float* codep = (float*)(smem + OFF_CODEP);
    float* codes = (float*)(smem + OFF_CODES);
    float* zs    = (float*)(smem + OFF_ZS);
    float* ep    = (float*)(smem + OFF_EP);

    const int tid  = threadIdx.x;
    const int b    = blockIdx.x;
    const int lane = tid & 31;
    const int warp = tid >> 5;

    // ---- cp.async W (pre-converted fp8) into smem ----
    {
        uint32_t ws = (uint32_t)__cvta_generic_to_shared(smem + OFF_W);
        const char* wg = (const char*)g_Wf8;
        for (int i = tid; i < SZ_W / 16; i += THREADS)
            asm volatile("cp.async.cg.shared.global [%0], [%1], 16;"
                         :: "r"(ws + i * 16), "l"(wg + i * 16));
        asm volatile("cp.async.commit_group;");
    }

    // ---- stage row pointers (padded to 256 rows) ----
    for (int i = tid; i < 2 * NCTX; i += THREADS) {
        int v = xs_xt[b * 2 * NCTX + i];
        uint64_t p = (uint64_t)(g_valf8 + (size_t)v * 128);
        if (i & 1) vtp[i >> 1] = p; else vsp[i >> 1] = p;
    }
    if (tid < NCTX)
        vpp[tid] = (uint64_t)(path_vocab + (size_t)path_idx[b * NCTX + tid] * 128);
    if (tid < 56) {
        vsp[NCTX + tid] = (uint64_t)g_valf8;
        vpp[NCTX + tid] = (uint64_t)path_vocab;
        vtp[NCTX + tid] = (uint64_t)g_valf8;
    }
    if (tid < D) avs[tid] = att_vec[tid];
    asm volatile("cp.async.wait_group 0;");
    __syncthreads();

    // ---- warp tiling: 2 m-warps (32 rows) x 8 n-warps (16 cols), m32n16 per warp ----
    const int mwarp = warp & 1;
    const int nwarp = warp >> 1;
    const int g  = lane >> 2;
    const int tg = lane & 3;

    const uint32_t ctx_s = (uint32_t)__cvta_generic_to_shared(smem + OFF_CTX);
    const uint32_t w_s   = (uint32_t)__cvta_generic_to_shared(smem + OFF_W);

    const uint32_t a_off0 = (uint32_t)((mwarp * 32 + (lane & 15)) * CTX_BSTRIDE + (lane >> 4) * 16);
    const uint32_t a_off1 = a_off0 + 16 * CTX_BSTRIDE;
    const int bc = ((lane >> 4) << 3) + (lane & 7);
    const uint32_t b_off = (uint32_t)((nwarp * 16 + bc) * CTX_BSTRIDE + ((lane >> 3) & 1) * 16);

    float av4[4];
#pragma unroll
    for (int jj = 0; jj < 2; jj++) {
        int col = nwarp * 16 + jj * 8 + tg * 2;
        av4[jj * 2]     = avs[col];
        av4[jj * 2 + 1] = avs[col + 1];
    }

    // gather role: 8 threads per row
    const int grow = tid >> 3;     // row within tile (0..63)
    const int gsub = tid & 7;

    float cpart[4] = {0.f, 0.f, 0.f, 0.f};
    float resum = 0.f;

    for (int t = 0; t < NTILES; t++) {
        const int n0 = t * TILE_N;
        const bool full = (t < NTILES - 1);

        // ---- gather tile t (tail: only rows < TAIL_ROWS are needed) ----
        if (full || grow < TAIL_ROWS) {
            const int gr = n0 + grow;
            const char* ps = (const char*)vsp[gr];
            const char* pp = (const char*)vpp[gr];
            const char* pt = (const char*)vtp[gr];
            uint4 vx  = ldg_nc_u4(ps + gsub * 16);
            uint4 vt2 = ldg_nc_u4(pt + gsub * 16);
            float4 f0 = ldg_nc_v4((const float*)pp + (gsub)      * 4);
            float4 f1 = ldg_nc_v4((const float*)pp + (gsub + 8)  * 4);
            float4 f2 = ldg_nc_v4((const float*)pp + (gsub + 16) * 4);
            float4 f3 = ldg_nc_v4((const float*)pp + (gsub + 24) * 4);
            unsigned char* crow = smem + OFF_CTX + grow * CTX_BSTRIDE;
            *(uint4*)(crow + gsub * 16)       = vx;
            *(uint4*)(crow + 256 + gsub * 16) = vt2;
            *(uint32_t*)(crow + 128 + (gsub)      * 4) = pack4_e4m3(f0);
            *(uint32_t*)(crow + 128 + (gsub + 8)  * 4) = pack4_e4m3(f1);
            *(uint32_t*)(crow + 128 + (gsub + 16) * 4) = pack4_e4m3(f2);
            *(uint32_t*)(crow + 128 + (gsub + 24) * 4) = pack4_e4m3(f3);
        }
        __syncthreads();

        // ---- GEMM: acc[m][jj][c], 12 k32-steps ----
        float acc[2][2][4];
#pragma unroll
        for (int m = 0; m < 2; m++)
#pragma unroll
            for (int jj = 0; jj < 2; jj++)
#pragma unroll
                for (int c = 0; c < 4; c++) acc[m][jj][c] = 0.f;

        if (full) {
#pragma unroll
            for (int kk = 0; kk < 12; kk++) {
                uint32_t a[2][4], bq[4];
                ldsm_x4(a[0][0], a[0][1], a[0][2], a[0][3], ctx_s + a_off0 + kk * 32);
                ldsm_x4(a[1][0], a[1][1], a[1][2], a[1][3], ctx_s + a_off1 + kk * 32);
                ldsm_x4(bq[0], bq[1], bq[2], bq[3], w_s + b_off + kk * 32);
#pragma unroll
                for (int m = 0; m < 2; m++) {
                    mma_f8(acc[m][0], a[m][0], a[m][1], a[m][2], a[m][3], bq[0], bq[1]);
                    mma_f8(acc[m][1], a[m][0], a[m][1], a[m][2], a[m][3], bq[2], bq[3]);
                }
            }
        } else if (mwarp == 0) {
            // tail: only rows 0-7 valid -> m=0 strip of mwarp==0 warps.
            // Stale ctx/acc elsewhere neutralized by esc=0.
#pragma unroll
            for (int kk = 0; kk < 12; kk++) {
                uint32_t a0[4], bq[4];
                ldsm_x4(a0[0], a0[1], a0[2], a0[3], ctx_s + a_off0 + kk * 32);
                ldsm_x4(bq[0], bq[1], bq[2], bq[3], w_s + b_off + kk * 32);
                mma_f8(acc[0][0], a0[0], a0[1], a0[2], a0[3], bq[0], bq[1]);
                mma_f8(acc[0][1], a0[0], a0[1], a0[2], a0[3], bq[2], bq[3]);
            }
        }

        // ---- tanh in place + score partials (tail: mwarp==0 only) ----
        if (full || mwarp == 0) {
#pragma unroll
            for (int m = 0; m < 2; m++)
#pragma unroll
                for (int jj = 0; jj < 2; jj++)
#pragma unroll
                    for (int c = 0; c < 4; c++)
                        acc[m][jj][c] = fast_tanhf(acc[m][jj][c]);

#pragma unroll
            for (int m = 0; m < 2; m++) {
#pragma unroll
                for (int h = 0; h < 2; h++) {
                    float p = 0.f;
#pragma unroll
                    for (int jj = 0; jj < 2; jj++) {
                        p += av4[jj * 2]     * acc[m][jj][h * 2];
                        p += av4[jj * 2 + 1] * acc[m][jj][h * 2 + 1];
                    }
                    p += __shfl_xor_sync(0xFFFFFFFFu, p, 1);
                    p += __shfl_xor_sync(0xFFFFFFFFu, p, 2);
                    if (tg == 0) {
                        int row = mwarp * 32 + m * 16 + h * 8 + g;
                        sp[row * 8 + nwarp] = p;
                    }
                }
            }
        }
        __syncthreads();

        if (tid < TILE_N) {
            float4 s0 = *(const float4*)&sp[tid * 8];
            float4 s1 = *(const float4*)&sp[tid * 8 + 4];
            float s = (s0.x + s0.y) + (s0.z + s0.w) + (s1.x + s1.y) + (s1.z + s1.w);
            float e;
            if (full) e = __expf(s);                       // n0+tid < 200 always
            else      e = (tid < TAIL_ROWS) ? __expf(s) : 0.f;
            esc[tid] = e;
            resum += e;
        }
        __syncthreads();

        // ---- weighted accumulation from registers (tail: mwarp==0 only) ----
        if (full || mwarp == 0) {
#pragma unroll
            for (int m = 0; m < 2; m++) {
#pragma unroll
                for (int h = 0; h < 2; h++) {
                    float e = esc[mwarp * 32 + m * 16 + h * 8 + g];
#pragma unroll
                    for (int jj = 0; jj < 2; jj++) {
                        cpart[jj * 2]     += e * acc[m][jj][h * 2];
                        cpart[jj * 2 + 1] += e * acc[m][jj][h * 2 + 1];
                    }
                }
            }
        }
        // next gather may overwrite ctx: all warps passed GEMM (sp-sync above).
    }

    // ---- reduce cpart across g, write per-mwarp col partials ----
#pragma unroll
    for (int off = 4; off < 32; off <<= 1)
#pragma unroll
        for (int i = 0; i < 4; i++)
            cpart[i] += __shfl_xor_sync(0xFFFFFFFFu, cpart[i], off);
    if (g == 0) {
#pragma unroll
        for (int jj = 0; jj < 2; jj++) {
            int col = nwarp * 16 + jj * 8 + tg * 2;
            codep[col * 2 + mwarp]       = cpart[jj * 2];
            codep[(col + 1) * 2 + mwarp] = cpart[jj * 2 + 1];
        }
    }
    if (tid < TILE_N) {
        float s = resum;
#pragma unroll
        for (int off = 16; off > 0; off >>= 1)
            s += __shfl_xor_sync(0xFFFFFFFFu, s, off);
        if (lane == 0) ep[warp] = s;
    }
    __syncthreads();

    float esum = ep[0] + ep[1];
    if (tid < D) {
        float c = codep[tid * 2] + codep[tid * 2 + 1];
        codes[tid] = c / esum;
    }
    __syncthreads();

    // ---- dense + sigmoid ----
    {
        const int grp = tid >> 7, dcol = tid & 127;
        float z = 0.f;
#pragma unroll 8
        for (int d2 = 0; d2 < 32; d2++) {
            int d = grp * 32 + d2;
            z += codes[d] * dense_w[d * OUTD + dcol];
        }
        if (grp != 0) zs[(grp - 1) * 128 + dcol] = z;
        __syncthreads();
        if (grp == 0) {
            float zz = z + zs[dcol] + zs[128 + dcol] + zs[256 + dcol] + dense_b[dcol];
            out[b * OUTD + dcol] = 1.f / (1.f + __expf(-zz));
        }
    }
}

extern "C" void kernel_launch(void* const* d_in, const int* in_sizes, int n_in,
                              void* d_out, int out_size)
{
    const int*   xs_xt       = (const int*)d_in[0];
    const int*   path_idx    = (const int*)d_in[1];
    const float* value_vocab = (const float*)d_in[2];
    const float* path_vocab  = (const float*)d_in[3];
    const float* W           = (const float*)d_in[4];
    const float* att_vec     = (const float*)d_in[5];
    const float* dense_w     = (const float*)d_in[6];
    const float* dense_b     = (const float*)d_in[7];
    float*       out         = (float*)d_out;

    prep_kernel<<<24 + 1563, 512>>>(W, value_vocab);

    cudaFuncSetAttribute(acv_fused_kernel,
                         cudaFuncAttributeMaxDynamicSharedMemorySize, SMEM_BYTES);
    acv_fused_kernel<<<1024, THREADS, SMEM_BYTES>>>(
        xs_xt, path_idx, path_vocab, att_vec,
        dense_w, dense_b, out);
}